// round 8
// baseline (speedup 1.0000x reference)
#include <cuda_runtime.h>
#include <math_constants.h>

#define NG      121
#define NHAND   21
#define NPAIR   126   // 21*6
#define NPPF    61    // point-pairs per face (last pair half-padded)
#define MAXB    8192

__device__ __align__(16) float2 g_acc[MAXB];   // (num, cnt) per batch
__device__ unsigned int g_sem = 0;             // returns to 0 at end of every launch

typedef unsigned long long ull;

// packed dual-fma: lo/hi halves are independent RN fmas (bit-identical to scalar fmaf)
__device__ __forceinline__ ull fma2(ull a, ull b, ull c)
{
    ull r;
    asm("fma.rn.f32x2 %0, %1, %2, %3;" : "=l"(r) : "l"(a), "l"(b), "l"(c));
    return r;
}
__device__ __forceinline__ float f2lo(ull v) { return __uint_as_float((unsigned)v); }
__device__ __forceinline__ float f2hi(ull v) { return __uint_as_float((unsigned)(v >> 32)); }
__device__ __forceinline__ ull bcast2(float x)
{
    unsigned u = __float_as_uint(x);
    return (ull)u | ((ull)u << 32);
}

// scalar g = yy - 2*zz; must match the f32x2 halves exactly (same fma chain order)
__device__ __forceinline__ float gval_s(float hx, float hy, float hz,
                                        float cx, float cy, float cz, float cw)
{
    return fmaf(hx, cx, fmaf(hy, cy, fmaf(hz, cz, cw)));
}

__global__ __launch_bounds__(128) void affinity_main(const float* __restrict__ poses,
                                                     float* __restrict__ out, int bs)
{
    const int b    = blockIdx.x;
    const int tid  = threadIdx.x;
    const int lane = tid & 31;
    const int warp = tid >> 5;
    const float* __restrict__ P = poses + b * 87;

    __shared__ float  s_pose[87];        // 21 hand + 8 obj, xyz
    __shared__ float  s_xx[NHAND];
    __shared__ float4 s_A[6*NPPF];       // (-2x_p, -2x_{p+1}, -2y_p, -2y_{p+1})
    __shared__ float4 s_B[6*NPPF];       // (-2z_p, -2z_{p+1},  yy_p,  yy_{p+1})
    __shared__ float  s_part[3*126];     // chunk partial minima [c][u][hh]
    __shared__ float  s_key[NPAIR];      // d2min = xx + gmin, flat = h*6+f
    __shared__ float  s_gb[NPAIR];       // exact gmin for argmin recovery
    __shared__ int    s_self[10];
    __shared__ float  s_seld[10];        // selected keys (d2min)
    __shared__ float4 s_cn[10];          // (m*nx, m*ny, m*nz, m)
    __shared__ float  s_geo[11];         // p1(3) dv(3) nd(3) dvn_e thr
    __shared__ float2 s_red[4];
    __shared__ int    s_flag;

    if (tid < 87) s_pose[tid] = P[tid];
    __syncthreads();

    if (tid < NHAND) {
        float x = s_pose[tid*3], y = s_pose[tid*3+1], z = s_pose[tid*3+2];
        s_xx[tid] = x*x + y*y + z*z;
    }

    const float* O = s_pose + NHAND*3;   // obj corners, 8 x 3

    // ---- Phase A: thread-per-gridpoint, scalar stores into pair layout ----
    if (tid < NG) {
        int iu = tid / 11;
        int iv = tid - iu * 11;
        float u = iu * 0.1f;
        float v = iv * 0.1f;
        float w0 = v * (1.0f - u);
        float w1 = v * u;
        float w2 = (1.0f - v) * (1.0f - u);
        float w3 = u * (1.0f - v);
        int pair = tid >> 1;
        int odd  = tid & 1;
        float Ox[8], Oy[8], Oz[8];
        #pragma unroll
        for (int k = 0; k < 8; k++) { Ox[k] = O[k*3]; Oy[k] = O[k*3+1]; Oz[k] = O[k*3+2]; }
        #define DOFACE(F, C0, C1, C2, C3) { \
            float x = w0*Ox[C0] + w1*Ox[C1] + w2*Ox[C2] + w3*Ox[C3]; \
            float y = w0*Oy[C0] + w1*Oy[C1] + w2*Oy[C2] + w3*Oy[C3]; \
            float z = w0*Oz[C0] + w1*Oz[C1] + w2*Oz[C2] + w3*Oz[C3]; \
            float yy = x*x + y*y + z*z; \
            float* Ap = (float*)(s_A + (F)*NPPF + pair); \
            float* Bp = (float*)(s_B + (F)*NPPF + pair); \
            Ap[odd] = -2.0f*x; Ap[2+odd] = -2.0f*y; \
            Bp[odd] = -2.0f*z; Bp[2+odd] = yy; }
        DOFACE(0, 0,1,2,3)
        DOFACE(1, 0,4,2,6)
        DOFACE(2, 0,1,4,5)
        DOFACE(3, 1,3,5,7)
        DOFACE(4, 2,3,6,7)
        DOFACE(5, 4,5,6,7)
        #undef DOFACE
    } else if (tid == 121) {
        // pad odd half of pair 60 on every face: g = INF (no NaN: hz*0+INF = INF)
        #pragma unroll
        for (int f = 0; f < 6; f++) {
            float* Ap = (float*)(s_A + f*NPPF + 60);
            float* Bp = (float*)(s_B + f*NPPF + 60);
            Ap[1] = 0.0f; Ap[3] = 0.0f;
            Bp[1] = 0.0f; Bp[3] = CUDART_INF_F;
        }
    }
    __syncthreads();

    // ---- Phase B: thread = (face, hand-triple, pair-chunk); packed f32x2 math.
    //      Chunks [0,21) [20,41) [40,61) — overlap harmless (min idempotent). ----
    if (tid < 126) {
        int c  = tid / 42;          // chunk 0..2
        int u  = tid - c * 42;      // unit 0..41
        int f  = u / 7;             // face 0..5
        int hg = u - f * 7;         // hand-group 0..6
        int h0 = hg * 3;

        ull hx0 = bcast2(s_pose[h0*3+0]), hy0 = bcast2(s_pose[h0*3+1]), hz0 = bcast2(s_pose[h0*3+2]);
        ull hx1 = bcast2(s_pose[h0*3+3]), hy1 = bcast2(s_pose[h0*3+4]), hz1 = bcast2(s_pose[h0*3+5]);
        ull hx2 = bcast2(s_pose[h0*3+6]), hy2 = bcast2(s_pose[h0*3+7]), hz2 = bcast2(s_pose[h0*3+8]);

        const ulonglong2* __restrict__ qa = (const ulonglong2*)(s_A + f*NPPF + c*20);
        const ulonglong2* __restrict__ qb = (const ulonglong2*)(s_B + f*NPPF + c*20);

        float m0e = CUDART_INF_F, m0o = CUDART_INF_F;
        float m1e = CUDART_INF_F, m1o = CUDART_INF_F;
        float m2e = CUDART_INF_F, m2o = CUDART_INF_F;
        #pragma unroll 21
        for (int p = 0; p < 21; p++) {
            ulonglong2 a = qa[p];   // a.x = (x_p,x_p1)*-2, a.y = (y_p,y_p1)*-2
            ulonglong2 bb = qb[p];  // bb.x = (z_p,z_p1)*-2, bb.y = (yy_p,yy_p1)
            ull g0 = fma2(hx0, a.x, fma2(hy0, a.y, fma2(hz0, bb.x, bb.y)));
            ull g1 = fma2(hx1, a.x, fma2(hy1, a.y, fma2(hz1, bb.x, bb.y)));
            ull g2 = fma2(hx2, a.x, fma2(hy2, a.y, fma2(hz2, bb.x, bb.y)));
            m0e = fminf(m0e, f2lo(g0)); m0o = fminf(m0o, f2hi(g0));
            m1e = fminf(m1e, f2lo(g1)); m1o = fminf(m1o, f2hi(g1));
            m2e = fminf(m2e, f2lo(g2)); m2o = fminf(m2o, f2hi(g2));
        }
        s_part[c*126 + u*3 + 0] = fminf(m0e, m0o);
        s_part[c*126 + u*3 + 1] = fminf(m1e, m1o);
        s_part[c*126 + u*3 + 2] = fminf(m2e, m2o);
    }
    __syncthreads();

    // Combine chunk partials: flat pair index = h*6 + f (matches reference order)
    if (tid < NPAIR) {
        int h  = tid / 6;
        int f  = tid - h * 6;
        int hg = h / 3;
        int hh = h - hg * 3;
        int o  = (f*7 + hg)*3 + hh;
        float best = fminf(fminf(s_part[o], s_part[126 + o]), s_part[252 + o]);
        s_gb [tid] = best;                         // exact min of g (min is assoc/comm)
        s_key[tid] = __fadd_rn(s_xx[h], best);     // d2min (monotone in g)
    }
    __syncthreads();

    // ---- Phase C (warp 0): stable 10-smallest; warp 1 computes geometry ----
    if (warp == 0) {
        float v0[4]; int i0[4];
        #pragma unroll
        for (int k = 0; k < 4; k++) {
            int t = tid + 32*k;
            if (t < NPAIR) { v0[k] = s_key[t]; i0[k] = t; }
            else           { v0[k] = CUDART_INF_F; i0[k] = 1 << 20; }
        }
        #pragma unroll
        for (int r = 0; r < 10; r++) {
            float bv = v0[0]; int bi = i0[0];
            #pragma unroll
            for (int k = 1; k < 4; k++)
                if (v0[k] < bv || (v0[k] == bv && i0[k] < bi)) { bv = v0[k]; bi = i0[k]; }
            #pragma unroll
            for (int off = 16; off; off >>= 1) {
                float ov = __shfl_xor_sync(0xffffffffu, bv, off);
                int   oi = __shfl_xor_sync(0xffffffffu, bi, off);
                if (ov < bv || (ov == bv && oi < bi)) { bv = ov; bi = oi; }
            }
            if (r == tid) { s_self[r] = bi; s_seld[r] = bv; }
            #pragma unroll
            for (int k = 0; k < 4; k++)
                if (i0[k] == bi) v0[k] = CUDART_INF_F;
        }
    } else if (warp == 1) {
        float p1x = (O[0]  + O[3]  + O[6]  + O[9] ) * 0.25f;
        float p1y = (O[1]  + O[4]  + O[7]  + O[10]) * 0.25f;
        float p1z = (O[2]  + O[5]  + O[8]  + O[11]) * 0.25f;
        float p2x = (O[12] + O[15] + O[18] + O[21]) * 0.25f;
        float p2y = (O[13] + O[16] + O[19] + O[22]) * 0.25f;
        float p2z = (O[14] + O[17] + O[20] + O[23]) * 0.25f;

        float l1 = 0.0f, l2 = 0.0f;
        #pragma unroll
        for (int e = 0; e < 4; e++) {
            int a = e, bb = (e + 1) & 3;
            float dx = O[a*3+0] - O[bb*3+0];
            float dy = O[a*3+1] - O[bb*3+1];
            float dz = O[a*3+2] - O[bb*3+2];
            l1 += sqrtf(dx*dx + dy*dy + dz*dz);
            int a2 = a + 4, b2 = bb + 4;
            dx = O[a2*3+0] - O[b2*3+0];
            dy = O[a2*3+1] - O[b2*3+1];
            dz = O[a2*3+2] - O[b2*3+2];
            l2 += sqrtf(dx*dx + dy*dy + dz*dz);
        }
        l1 *= 0.25f; l2 *= 0.25f;
        float thr = ((l1 + l2) * 0.5f) * 0.2f;

        float dvx = p2x - p1x, dvy = p2y - p1y, dvz = p2z - p1z;
        float dvn = sqrtf(dvx*dvx + dvy*dvy + dvz*dvz);
        float dvn_e = dvn + 1e-5f;

        if (lane == 0) {
            s_geo[0] = p1x; s_geo[1] = p1y; s_geo[2] = p1z;
            s_geo[3] = dvx; s_geo[4] = dvy; s_geo[5] = dvz;
            s_geo[6] = dvx / dvn_e; s_geo[7] = dvy / dvn_e; s_geo[8] = dvz / dvn_e;
            s_geo[9] = dvn_e; s_geo[10] = thr;
        }
    }
    __syncthreads();

    // ---- Phase D: argmin recovery by exact-match ballot + normal contribution ----
    {
        float p1x = s_geo[0], p1y = s_geo[1], p1z = s_geo[2];
        float dvx = s_geo[3], dvy = s_geo[4], dvz = s_geo[5];
        float ndx = s_geo[6], ndy = s_geo[7], ndz = s_geo[8];
        float dvn_e = s_geo[9], thr = s_geo[10];

        for (int c = warp; c < 10; c += 4) {
            int flat = s_self[c];
            int h = flat / 6;
            int f = flat - h * 6;
            float hx = s_pose[h*3], hy = s_pose[h*3+1], hz = s_pose[h*3+2];
            float gb = s_gb[flat];
            const float4* __restrict__ qa = s_A + f*NPPF;
            const float4* __restrict__ qb = s_B + f*NPPF;

            int p = 0;
            #pragma unroll
            for (int k = 0; k < 4; k++) {
                int pp = k*32 + lane;
                bool hit = false;
                if (pp < NG) {
                    float4 a4 = qa[pp >> 1];
                    float4 b4 = qb[pp >> 1];
                    int od = pp & 1;
                    float cx = od ? a4.y : a4.x;
                    float cy = od ? a4.w : a4.z;
                    float cz = od ? b4.y : b4.x;
                    float cw = od ? b4.w : b4.z;
                    hit = (gval_s(hx, hy, hz, cx, cy, cz, cw) == gb);
                }
                unsigned m = __ballot_sync(0xffffffffu, hit);
                if (m) { p = k*32 + (__ffs(m) - 1); break; }   // first occurrence
            }

            if (lane == 0) {
                float4 a4 = qa[p >> 1];
                float4 b4 = qb[p >> 1];
                int od = p & 1;
                float cx = -0.5f * (od ? a4.y : a4.x);   // exact coord recovery
                float cy = -0.5f * (od ? a4.w : a4.z);
                float cz = -0.5f * (od ? b4.y : b4.x);
                float vx = cx - p1x, vy = cy - p1y, vz = cz - p1z;
                float inner = dvx*vx + dvy*vy + dvz*vz;
                float tt = inner / dvn_e;
                float rx = p1x + ndx * tt;
                float ry = p1y + ndy * tt;
                float rz = p1z + ndz * tt;
                float nx = cx - rx, ny = cy - ry, nz = cz - rz;
                float nn = sqrtf(nx*nx + ny*ny + nz*nz) + 1e-5f;
                nx /= nn; ny /= nn; nz /= nn;
                float dist = sqrtf(s_seld[c] + 1e-6f);
                float m = (dist < thr) ? 1.0f : 0.0f;
                s_cn[c] = make_float4(m*nx, m*ny, m*nz, m);
            }
        }
    }
    __syncthreads();

    // ---- Per-batch result: |sum m n|^2 and (sum m)^2 ----
    if (tid < 32) {
        float sx = 0.0f, sy = 0.0f, sz = 0.0f, sc = 0.0f;
        if (tid < 10) {
            float4 v = s_cn[tid];
            sx = v.x; sy = v.y; sz = v.z; sc = v.w;
        }
        #pragma unroll
        for (int off = 16; off; off >>= 1) {
            sx += __shfl_xor_sync(0xffffffffu, sx, off);
            sy += __shfl_xor_sync(0xffffffffu, sy, off);
            sz += __shfl_xor_sync(0xffffffffu, sz, off);
            sc += __shfl_xor_sync(0xffffffffu, sc, off);
        }
        if (tid == 0) {
            g_acc[b] = make_float2(sx*sx + sy*sy + sz*sz, sc*sc);
            __threadfence();                       // release g_acc[b]
            unsigned old = atomicAdd(&g_sem, 1u);
            s_flag = (old == (unsigned)(bs - 1));
        }
    }
    __syncthreads();

    // ---- Last block: deterministic final reduction, semaphore self-reset ----
    if (s_flag) {
        __threadfence();                           // acquire all g_acc
        float a = 0.0f, c = 0.0f;
        const float4* __restrict__ A = (const float4*)g_acc;
        int n4 = bs >> 1;
        for (int i = tid; i < n4; i += 128) {
            float4 v = A[i];
            a += v.x + v.z;
            c += v.y + v.w;
        }
        if ((bs & 1) && tid == 0) { float2 v = g_acc[bs - 1]; a += v.x; c += v.y; }
        #pragma unroll
        for (int off = 16; off; off >>= 1) {
            a += __shfl_xor_sync(0xffffffffu, a, off);
            c += __shfl_xor_sync(0xffffffffu, c, off);
        }
        if (lane == 0) s_red[warp] = make_float2(a, c);
        __syncthreads();
        if (tid == 0) {
            a = s_red[0].x + s_red[1].x + s_red[2].x + s_red[3].x;
            c = s_red[0].y + s_red[1].y + s_red[2].y + s_red[3].y;
            out[0] = a / (c + 1.0f);
            atomicExch(&g_sem, 0u);                // reset for next graph replay
        }
    }
}

extern "C" void kernel_launch(void* const* d_in, const int* in_sizes, int n_in,
                              void* d_out, int out_size)
{
    const float* poses = (const float*)d_in[0];
    int bs = in_sizes[0] / 87;
    if (bs > MAXB) bs = MAXB;
    affinity_main<<<bs, 128>>>(poses, (float*)d_out, bs);
}

// round 9
// speedup vs baseline: 1.1267x; 1.1267x over previous
#include <cuda_runtime.h>
#include <math_constants.h>

#define NG      121
#define NHAND   21
#define NPAIR   126   // 21*6
#define NOBJ    726   // 6*121
#define MAXB    8192

__device__ __align__(16) float2 g_acc[MAXB];   // (num, cnt) per batch
__device__ unsigned int g_sem = 0;             // returns to 0 at end of every launch

// g = yy - 2*zz. Must be bit-identical in phase B (min) and phase D (argmin match).
__device__ __forceinline__ float gval(float hx, float hy, float hz, float4 c)
{
    return fmaf(hx, c.x, fmaf(hy, c.y, fmaf(hz, c.z, c.w)));
}

__global__ __launch_bounds__(128, 12) void affinity_main(const float* __restrict__ poses,
                                                         float* __restrict__ out, int bs)
{
    const int b    = blockIdx.x;
    const int tid  = threadIdx.x;
    const int lane = tid & 31;
    const int warp = tid >> 5;
    const float* __restrict__ P = poses + b * 87;

    __shared__ float  s_pose[87];     // 21 hand + 8 obj, xyz
    __shared__ float  s_xx[NHAND];
    __shared__ float4 s_pts[NOBJ];    // (-2x, -2y, -2z, yy)
    __shared__ float  s_part[3*126];  // chunk partial minima [c][u][hh]
    __shared__ float  s_key[NPAIR];   // d2min = xx + gmin, flat = h*6+f
    __shared__ float  s_gb[NPAIR];    // exact gmin for argmin recovery
    __shared__ int    s_self[10];
    __shared__ float  s_seld[10];     // selected keys (d2min)
    __shared__ float4 s_cn[10];       // (m*nx, m*ny, m*nz, m)
    __shared__ float  s_geo[11];      // p1(3) dv(3) nd(3) dvn_e thr
    __shared__ float2 s_red[4];
    __shared__ int    s_flag;

    if (tid < 87) s_pose[tid] = P[tid];
    __syncthreads();

    if (tid < NHAND) {
        float x = s_pose[tid*3], y = s_pose[tid*3+1], z = s_pose[tid*3+2];
        s_xx[tid] = x*x + y*y + z*z;
    }

    const float* O = s_pose + NHAND*3;   // obj corners, 8 x 3

    // ---- Phase A: thread-per-gridpoint, 6 faces unrolled with literal corners ----
    if (tid < NG) {
        int iu = tid / 11;
        int iv = tid - iu * 11;
        float u = iu * 0.1f;
        float v = iv * 0.1f;
        float w0 = v * (1.0f - u);
        float w1 = v * u;
        float w2 = (1.0f - v) * (1.0f - u);
        float w3 = u * (1.0f - v);
        float Ox[8], Oy[8], Oz[8];
        #pragma unroll
        for (int k = 0; k < 8; k++) { Ox[k] = O[k*3]; Oy[k] = O[k*3+1]; Oz[k] = O[k*3+2]; }
        #define DOFACE(F, C0, C1, C2, C3) { \
            float x = w0*Ox[C0] + w1*Ox[C1] + w2*Ox[C2] + w3*Ox[C3]; \
            float y = w0*Oy[C0] + w1*Oy[C1] + w2*Oy[C2] + w3*Oy[C3]; \
            float z = w0*Oz[C0] + w1*Oz[C1] + w2*Oz[C2] + w3*Oz[C3]; \
            float yy = x*x + y*y + z*z; \
            s_pts[(F)*NG + tid] = make_float4(-2.0f*x, -2.0f*y, -2.0f*z, yy); }
        DOFACE(0, 0,1,2,3)
        DOFACE(1, 0,4,2,6)
        DOFACE(2, 0,1,4,5)
        DOFACE(3, 1,3,5,7)
        DOFACE(4, 2,3,6,7)
        DOFACE(5, 4,5,6,7)
        #undef DOFACE
    }
    __syncthreads();

    // ---- Phase B: each thread = (face, hand-triple, point-chunk).
    //      One LDS.128 per point amortized over 3 hands. ----
    if (tid < 126) {
        int c  = tid / 42;          // chunk 0..2
        int u  = tid - c * 42;      // unit 0..41
        int f  = u / 7;             // face 0..5
        int hg = u - f * 7;         // hand-group 0..6
        int h0 = hg * 3;

        float hx0 = s_pose[h0*3+0], hy0 = s_pose[h0*3+1], hz0 = s_pose[h0*3+2];
        float hx1 = s_pose[h0*3+3], hy1 = s_pose[h0*3+4], hz1 = s_pose[h0*3+5];
        float hx2 = s_pose[h0*3+6], hy2 = s_pose[h0*3+7], hz2 = s_pose[h0*3+8];

        const float4* __restrict__ q = s_pts + f * NG + c * 40;
        float m0 = CUDART_INF_F, m1 = CUDART_INF_F, m2 = CUDART_INF_F;
        #pragma unroll 10
        for (int p = 0; p < 40; p++) {
            float4 pt = q[p];
            m0 = fminf(m0, gval(hx0, hy0, hz0, pt));
            m1 = fminf(m1, gval(hx1, hy1, hz1, pt));
            m2 = fminf(m2, gval(hx2, hy2, hz2, pt));
        }
        if (c == 2) {               // point 120
            float4 pt = q[40];
            m0 = fminf(m0, gval(hx0, hy0, hz0, pt));
            m1 = fminf(m1, gval(hx1, hy1, hz1, pt));
            m2 = fminf(m2, gval(hx2, hy2, hz2, pt));
        }
        s_part[c*126 + u*3 + 0] = m0;
        s_part[c*126 + u*3 + 1] = m1;
        s_part[c*126 + u*3 + 2] = m2;
    }
    __syncthreads();

    // Combine chunk partials: flat pair index = h*6 + f (matches reference order)
    if (tid < NPAIR) {
        int h  = tid / 6;
        int f  = tid - h * 6;
        int hg = h / 3;
        int hh = h - hg * 3;
        int o  = (f*7 + hg)*3 + hh;
        float best = fminf(fminf(s_part[o], s_part[126 + o]), s_part[252 + o]);
        s_gb [tid] = best;                         // exact min of g (min is assoc/comm)
        s_key[tid] = __fadd_rn(s_xx[h], best);     // d2min (monotone in g)
    }
    __syncthreads();

    // ---- Phase C (warp 0): stable 10-smallest of the 126 keys
    //      Overlapped: warp 1 computes contact geometry into s_geo ----
    if (warp == 0) {
        float v0[4]; int i0[4];
        #pragma unroll
        for (int k = 0; k < 4; k++) {
            int t = tid + 32*k;
            if (t < NPAIR) { v0[k] = s_key[t]; i0[k] = t; }
            else           { v0[k] = CUDART_INF_F; i0[k] = 1 << 20; }
        }
        #pragma unroll
        for (int r = 0; r < 10; r++) {
            float bv = v0[0]; int bi = i0[0];
            #pragma unroll
            for (int k = 1; k < 4; k++)
                if (v0[k] < bv || (v0[k] == bv && i0[k] < bi)) { bv = v0[k]; bi = i0[k]; }
            #pragma unroll
            for (int off = 16; off; off >>= 1) {
                float ov = __shfl_xor_sync(0xffffffffu, bv, off);
                int   oi = __shfl_xor_sync(0xffffffffu, bi, off);
                if (ov < bv || (ov == bv && oi < bi)) { bv = ov; bi = oi; }
            }
            if (r == tid) { s_self[r] = bi; s_seld[r] = bv; }
            #pragma unroll
            for (int k = 0; k < 4; k++)
                if (i0[k] == bi) v0[k] = CUDART_INF_F;
        }
    } else if (warp == 1) {
        float p1x = (O[0]  + O[3]  + O[6]  + O[9] ) * 0.25f;
        float p1y = (O[1]  + O[4]  + O[7]  + O[10]) * 0.25f;
        float p1z = (O[2]  + O[5]  + O[8]  + O[11]) * 0.25f;
        float p2x = (O[12] + O[15] + O[18] + O[21]) * 0.25f;
        float p2y = (O[13] + O[16] + O[19] + O[22]) * 0.25f;
        float p2z = (O[14] + O[17] + O[20] + O[23]) * 0.25f;

        float l1 = 0.0f, l2 = 0.0f;
        #pragma unroll
        for (int e = 0; e < 4; e++) {
            int a = e, bb = (e + 1) & 3;
            float dx = O[a*3+0] - O[bb*3+0];
            float dy = O[a*3+1] - O[bb*3+1];
            float dz = O[a*3+2] - O[bb*3+2];
            l1 += sqrtf(dx*dx + dy*dy + dz*dz);
            int a2 = a + 4, b2 = bb + 4;
            dx = O[a2*3+0] - O[b2*3+0];
            dy = O[a2*3+1] - O[b2*3+1];
            dz = O[a2*3+2] - O[b2*3+2];
            l2 += sqrtf(dx*dx + dy*dy + dz*dz);
        }
        l1 *= 0.25f; l2 *= 0.25f;
        float thr = ((l1 + l2) * 0.5f) * 0.2f;

        float dvx = p2x - p1x, dvy = p2y - p1y, dvz = p2z - p1z;
        float dvn = sqrtf(dvx*dvx + dvy*dvy + dvz*dvz);
        float dvn_e = dvn + 1e-5f;

        if (lane == 0) {
            s_geo[0] = p1x; s_geo[1] = p1y; s_geo[2] = p1z;
            s_geo[3] = dvx; s_geo[4] = dvy; s_geo[5] = dvz;
            s_geo[6] = dvx / dvn_e; s_geo[7] = dvy / dvn_e; s_geo[8] = dvz / dvn_e;
            s_geo[9] = dvn_e; s_geo[10] = thr;
        }
    }
    __syncthreads();

    // ---- Phase D: argmin recovery by exact-match ballot + normal contribution ----
    {
        float p1x = s_geo[0], p1y = s_geo[1], p1z = s_geo[2];
        float dvx = s_geo[3], dvy = s_geo[4], dvz = s_geo[5];
        float ndx = s_geo[6], ndy = s_geo[7], ndz = s_geo[8];
        float dvn_e = s_geo[9], thr = s_geo[10];

        for (int c = warp; c < 10; c += 4) {
            int flat = s_self[c];
            int h = flat / 6;
            int f = flat - h * 6;
            float hx = s_pose[h*3], hy = s_pose[h*3+1], hz = s_pose[h*3+2];
            float gb = s_gb[flat];
            const float4* __restrict__ q = s_pts + f * NG;

            int p = 0;
            #pragma unroll
            for (int k = 0; k < 4; k++) {
                int pp = k*32 + lane;
                bool hit = (pp < NG) && (gval(hx, hy, hz, q[pp]) == gb);
                unsigned m = __ballot_sync(0xffffffffu, hit);
                if (m) { p = k*32 + (__ffs(m) - 1); break; }   // first occurrence
            }

            if (lane == 0) {
                float4 c4 = q[p];
                float cx = -0.5f * c4.x;   // exact recovery of coords
                float cy = -0.5f * c4.y;
                float cz = -0.5f * c4.z;
                float vx = cx - p1x, vy = cy - p1y, vz = cz - p1z;
                float inner = dvx*vx + dvy*vy + dvz*vz;
                float tt = inner / dvn_e;
                float rx = p1x + ndx * tt;
                float ry = p1y + ndy * tt;
                float rz = p1z + ndz * tt;
                float nx = cx - rx, ny = cy - ry, nz = cz - rz;
                float nn = sqrtf(nx*nx + ny*ny + nz*nz) + 1e-5f;
                nx /= nn; ny /= nn; nz /= nn;
                float dist = sqrtf(s_seld[c] + 1e-6f);
                float m = (dist < thr) ? 1.0f : 0.0f;
                s_cn[c] = make_float4(m*nx, m*ny, m*nz, m);
            }
        }
    }
    __syncthreads();

    // ---- Per-batch result: |sum m n|^2 and (sum m)^2 ----
    if (tid < 32) {
        float sx = 0.0f, sy = 0.0f, sz = 0.0f, sc = 0.0f;
        if (tid < 10) {
            float4 v = s_cn[tid];
            sx = v.x; sy = v.y; sz = v.z; sc = v.w;
        }
        #pragma unroll
        for (int off = 16; off; off >>= 1) {
            sx += __shfl_xor_sync(0xffffffffu, sx, off);
            sy += __shfl_xor_sync(0xffffffffu, sy, off);
            sz += __shfl_xor_sync(0xffffffffu, sz, off);
            sc += __shfl_xor_sync(0xffffffffu, sc, off);
        }
        if (tid == 0) {
            g_acc[b] = make_float2(sx*sx + sy*sy + sz*sz, sc*sc);
            __threadfence();                       // release g_acc[b]
            unsigned old = atomicAdd(&g_sem, 1u);
            s_flag = (old == (unsigned)(bs - 1));
        }
    }
    __syncthreads();

    // ---- Last block: deterministic final reduction, semaphore self-reset ----
    if (s_flag) {
        __threadfence();                           // acquire all g_acc
        float a = 0.0f, c = 0.0f;
        const float4* __restrict__ A = (const float4*)g_acc;
        int n4 = bs >> 1;
        for (int i = tid; i < n4; i += 128) {
            float4 v = A[i];
            a += v.x + v.z;
            c += v.y + v.w;
        }
        if ((bs & 1) && tid == 0) { float2 v = g_acc[bs - 1]; a += v.x; c += v.y; }
        #pragma unroll
        for (int off = 16; off; off >>= 1) {
            a += __shfl_xor_sync(0xffffffffu, a, off);
            c += __shfl_xor_sync(0xffffffffu, c, off);
        }
        if (lane == 0) s_red[warp] = make_float2(a, c);
        __syncthreads();
        if (tid == 0) {
            a = s_red[0].x + s_red[1].x + s_red[2].x + s_red[3].x;
            c = s_red[0].y + s_red[1].y + s_red[2].y + s_red[3].y;
            out[0] = a / (c + 1.0f);
            atomicExch(&g_sem, 0u);                // reset for next graph replay
        }
    }
}

extern "C" void kernel_launch(void* const* d_in, const int* in_sizes, int n_in,
                              void* d_out, int out_size)
{
    const float* poses = (const float*)d_in[0];
    int bs = in_sizes[0] / 87;
    if (bs > MAXB) bs = MAXB;
    affinity_main<<<bs, 128>>>(poses, (float*)d_out, bs);
}